// round 2
// baseline (speedup 1.0000x reference)
#include <cuda_runtime.h>
#include <cstdint>

#define Dn 1024
#define Vn 64
#define TMn 32
#define NTHREADS 256
#define KCHUNK 128
#define NCHUNKS (Dn / KCHUNK)
#define PTHRESH 1e-8f

// head_weight transposed into d-pair-major layout: g_wt[dp*64 + v] = (hw[v][2dp], hw[v][2dp+1])
__device__ __align__(16) float2 g_wt[(Dn / 2) * Vn];

__global__ void k_transpose_w(const float* __restrict__ hw) {
    int i = blockIdx.x * blockDim.x + threadIdx.x;   // 0 .. 32767
    if (i >= Vn * (Dn / 2)) return;
    int v  = i >> 9;      // 512 pairs per vocab row
    int dp = i & 511;
    float2 p;
    p.x = hw[v * Dn + 2 * dp];
    p.y = hw[v * Dn + 2 * dp + 1];
    g_wt[dp * Vn + v] = p;
}

__device__ __forceinline__ unsigned long long ffma2(unsigned long long a,
                                                    unsigned long long b,
                                                    unsigned long long c) {
    unsigned long long d;
    asm("fma.rn.f32x2 %0, %1, %2, %3;" : "=l"(d) : "l"(a), "l"(b), "l"(c));
    return d;
}
__device__ __forceinline__ float f2lo(unsigned long long a) { return __uint_as_float((unsigned)a); }
__device__ __forceinline__ float f2hi(unsigned long long a) { return __uint_as_float((unsigned)(a >> 32)); }

// sigmoid for |z| <~ 0.3 (gate scale 0.01): odd poly, max err < 5e-8; exact fallback for tails.
__device__ __forceinline__ float sigmoid_f(float z) {
    float z2 = z * z;
    float p = fmaf(z, fmaf(z2, fmaf(z2, 0.00208333333f, -0.0208333333f), 0.25f), 0.5f);
    if (fabsf(z) > 0.35f) p = 1.0f / (1.0f + __expf(-z));
    return p;
}

__global__ void __launch_bounds__(NTHREADS, 1)
k_fused(const float* __restrict__ xg, const int* __restrict__ iw,
        const float* __restrict__ emb, const float* __restrict__ gate,
        const float* __restrict__ sgate, float* __restrict__ out,
        int idx_off, int has_idx)
{
    extern __shared__ char smem_raw[];
    float2* ws  = (float2*)smem_raw;                          // 32 KB  W chunk [64 dp][64 v] pairs
    float*  x1s = (float*)(smem_raw + 32768);                 // 128 KB x1 tile [32][1024]
    float*  gts = (float*)(smem_raw + 32768 + 131072);        // 4 KB gate
    float*  sgs = gts + Dn;                                   // 4 KB soft_gate

    const int tid  = threadIdx.x;
    const int lane = tid & 31;
    const int w    = tid >> 5;
    const int t0   = blockIdx.x * TMn;

    for (int i = tid; i < Dn; i += NTHREADS) { gts[i] = gate[i]; sgs[i] = sgate[i]; }

    // idx dtype detection: int64 storage => all high words zero; int32 => random values 0..63.
    int oddnz = (iw[2 * tid + 1] != 0);
    int is32  = __syncthreads_or(oddnz);   // also fences the gate staging

    // ---------------- Phase A: gate blend, x1 into smem, soft-gate mean ----------------
    float sgv[4];
    #pragma unroll
    for (int j = 0; j < 4; j++) {
        const int tl = w * 4 + j;
        const int tg = t0 + tl;
        const float* xr = xg + (size_t)tg * Dn;
        float* xs = x1s + tl * Dn;
        float s = 0.f;
        #pragma unroll 8
        for (int k = 0; k < 32; k++) {
            int d = lane + 32 * k;
            float xv = xr[d];
            xs[d] = xv;                      // stash raw x (warp-private rows)
            s += sigmoid_f(xv * gts[d]);
        }
        #pragma unroll
        for (int o = 16; o; o >>= 1) s += __shfl_xor_sync(0xffffffffu, s, o);
        float g = s * (1.0f / 1024.0f);

        int it = is32 ? iw[tg] : iw[2 * tg];
        it = min(max(it, 0), Vn - 1);
        const float* er = emb + (size_t)it * Dn;

        float ss = 0.f;
        #pragma unroll 8
        for (int k = 0; k < 32; k++) {
            int d = lane + 32 * k;
            float xv = xs[d];
            float x1 = fmaf(er[d] - xv, g, xv);   // x*(1-g) + emb*g
            xs[d] = x1;
            ss += sigmoid_f(x1 * sgs[d]);
        }
        #pragma unroll
        for (int o = 16; o; o >>= 1) ss += __shfl_xor_sync(0xffffffffu, ss, o);
        sgv[j] = ss * (1.0f / 1024.0f);
    }

    // ---------------- Phase B: logits GEMM, fp32 via packed f32x2 FFMA ----------------
    // warp -> 4 tokens; lane -> vocab pair (2*lane, 2*lane+1); acc over d-pairs.
    unsigned long long acc[4][2];
    #pragma unroll
    for (int j = 0; j < 4; j++) { acc[j][0] = 0ull; acc[j][1] = 0ull; }

    const ulonglong2* wsv = (const ulonglong2*)ws;
    for (int kc = 0; kc < NCHUNKS; kc++) {
        __syncthreads();
        const float4* src = (const float4*)(g_wt + kc * (KCHUNK / 2) * Vn);
        float4* dst = (float4*)ws;
        #pragma unroll
        for (int i = 0; i < 8; i++) dst[tid + i * NTHREADS] = src[tid + i * NTHREADS];
        __syncthreads();

        const ulonglong2* xrow[4];
        #pragma unroll
        for (int j = 0; j < 4; j++)
            xrow[j] = (const ulonglong2*)(x1s + (w * 4 + j) * Dn + kc * KCHUNK);

        #pragma unroll 8
        for (int dp2 = 0; dp2 < 32; dp2++) {
            ulonglong2 wa = wsv[(2 * dp2) * 32 + lane];       // d-pair 2*dp2, v = 2l,2l+1
            ulonglong2 wb = wsv[(2 * dp2 + 1) * 32 + lane];   // d-pair 2*dp2+1
            #pragma unroll
            for (int j = 0; j < 4; j++) {
                ulonglong2 xj = xrow[j][dp2];                 // two d-pairs (broadcast LDS.128)
                acc[j][0] = ffma2(xj.x, wa.x, acc[j][0]);
                acc[j][1] = ffma2(xj.x, wa.y, acc[j][1]);
                acc[j][0] = ffma2(xj.y, wb.x, acc[j][0]);
                acc[j][1] = ffma2(xj.y, wb.y, acc[j][1]);
            }
        }
    }

    // ---------------- Phase C: argmax + peaked softmax (sparse support) ----------------
    float p0a[4], p1a[4];
    unsigned m0a[4], m1a[4];
    #pragma unroll
    for (int j = 0; j < 4; j++) {
        float l0 = f2lo(acc[j][0]) + f2hi(acc[j][0]);
        float l1 = f2lo(acc[j][1]) + f2hi(acc[j][1]);
        float m = l0; int mi = 2 * lane;
        if (l1 > m) { m = l1; mi = 2 * lane + 1; }
        #pragma unroll
        for (int o = 16; o; o >>= 1) {
            float om = __shfl_xor_sync(0xffffffffu, m, o);
            int  omi = __shfl_xor_sync(0xffffffffu, mi, o);
            if (om > m || (om == m && omi < mi)) { m = om; mi = omi; }   // first-index tie rule
        }
        float e0 = __expf(l0 - m), e1 = __expf(l1 - m);
        float den = e0 + e1;
        #pragma unroll
        for (int o = 16; o; o >>= 1) den += __shfl_xor_sync(0xffffffffu, den, o);
        float rd = 1.0f / den;
        float p0 = e0 * rd, p1 = e1 * rd;
        p0a[j] = p0; p1a[j] = p1;
        m0a[j] = __ballot_sync(0xffffffffu, p0 > PTHRESH);
        m1a[j] = __ballot_sync(0xffffffffu, p1 > PTHRESH);
        if (has_idx && lane == 0) out[(size_t)idx_off + (t0 + w * 4 + j)] = (float)mi;
    }

    // ---------------- Phase D: sparse soft_emb gather + final blend + store ----------------
    #pragma unroll
    for (int j = 0; j < 4; j++) {
        const int tl = w * 4 + j;
        const int tg = t0 + tl;
        const float sgj = sgv[j];
        const float* xs = x1s + tl * Dn;
        float* orow = out + (size_t)tg * Dn;
        for (int c = 0; c < 4; c++) {
            float av[8];
            #pragma unroll
            for (int i = 0; i < 8; i++) av[i] = 0.f;
            unsigned mm = m0a[j];
            while (mm) {                         // trip count uniform across warp (from ballot)
                int b = __ffs(mm) - 1; mm &= mm - 1;
                float p = __shfl_sync(0xffffffffu, p0a[j], b);
                const float* er = emb + (size_t)(2 * b) * Dn + c * 256 + lane;
                #pragma unroll
                for (int i = 0; i < 8; i++) av[i] = fmaf(p, __ldg(er + 32 * i), av[i]);
            }
            mm = m1a[j];
            while (mm) {
                int b = __ffs(mm) - 1; mm &= mm - 1;
                float p = __shfl_sync(0xffffffffu, p1a[j], b);
                const float* er = emb + (size_t)(2 * b + 1) * Dn + c * 256 + lane;
                #pragma unroll
                for (int i = 0; i < 8; i++) av[i] = fmaf(p, __ldg(er + 32 * i), av[i]);
            }
            #pragma unroll
            for (int i = 0; i < 8; i++) {
                int d = c * 256 + lane + 32 * i;
                float xv = xs[d];
                orow[d] = fmaf(sgj, av[i] - xv, xv);   // x1*(1-sg) + soft_emb*sg
            }
        }
    }
}

extern "C" void kernel_launch(void* const* d_in, const int* in_sizes, int n_in,
                              void* d_out, int out_size) {
    (void)n_in;
    const float* x     = (const float*)d_in[0];
    const int*   idx   = (const int*)d_in[1];
    const float* emb   = (const float*)d_in[2];
    const float* hw    = (const float*)d_in[3];
    const float* gate  = (const float*)d_in[4];
    const float* sgate = (const float*)d_in[5];
    float* out = (float*)d_out;

    const int n_tok   = in_sizes[0] / Dn;          // 32768
    const int idx_off = in_sizes[0];               // x-part element count
    const int has_idx = (out_size >= idx_off + n_tok) ? 1 : 0;

    const int smem_bytes = 32768 + TMn * Dn * 4 + 2 * Dn * 4;   // 172032
    cudaFuncSetAttribute(k_fused, cudaFuncAttributeMaxDynamicSharedMemorySize, smem_bytes);

    k_transpose_w<<<(Vn * (Dn / 2) + 255) / 256, 256>>>(hw);
    k_fused<<<n_tok / TMn, NTHREADS, smem_bytes>>>(x, idx, emb, gate, sgate, out,
                                                   idx_off, has_idx);
}

// round 3
// speedup vs baseline: 2.3383x; 2.3383x over previous
#include <cuda_runtime.h>
#include <cstdint>

#define Dn 1024
#define Vn 64
#define TM 32
#define NT 512
#define XP 1025              // padded x1 row stride (floats)
#define CD 128               // d-chunk
#define NCH 8
#define TPAD 65
#define TILE_F (16 * TPAD)   // 1040 floats per partial tile
#define PTHRESH 1e-8f

// head_weight transposed: g_wt[d*64 + v] = hw[v*1024 + d]
__device__ __align__(16) float g_wt[Dn * Vn];

__global__ void k_tr(const float* __restrict__ hw) {
    __shared__ float t[64][65];
    const int d0 = blockIdx.x * 64;
    const int c  = threadIdx.x & 63;
    const int r4 = threadIdx.x >> 6;
    #pragma unroll
    for (int i = 0; i < 16; i++) {
        int v = r4 * 16 + i;
        t[c][v] = hw[v * Dn + d0 + c];
    }
    __syncthreads();
    #pragma unroll
    for (int i = 0; i < 16; i++) {
        int dd = r4 * 16 + i;
        g_wt[(d0 + dd) * Vn + c] = t[dd][c];
    }
}

__device__ __forceinline__ unsigned long long ffma2(unsigned long long a,
                                                    unsigned long long b,
                                                    unsigned long long c) {
    unsigned long long d;
    asm("fma.rn.f32x2 %0, %1, %2, %3;" : "=l"(d) : "l"(a), "l"(b), "l"(c));
    return d;
}
__device__ __forceinline__ unsigned long long packdup(float x) {
    unsigned long long d;
    unsigned u = __float_as_uint(x);
    asm("mov.b64 %0, {%1, %1};" : "=l"(d) : "r"(u));
    return d;
}
__device__ __forceinline__ float f2lo(unsigned long long a) { return __uint_as_float((unsigned)a); }
__device__ __forceinline__ float f2hi(unsigned long long a) { return __uint_as_float((unsigned)(a >> 32)); }

__device__ __forceinline__ float sigmoid_f(float z) {
    float z2 = z * z;
    float p = fmaf(z, fmaf(z2, fmaf(z2, 0.00208333333f, -0.0208333333f), 0.25f), 0.5f);
    if (fabsf(z) > 0.35f) p = 1.0f / (1.0f + __expf(-z));
    return p;
}

__global__ void __launch_bounds__(NT, 1)
k_fused(const float* __restrict__ xg, const int* __restrict__ iw,
        const float* __restrict__ emb, const float* __restrict__ gate,
        const float* __restrict__ sgate, float* __restrict__ out,
        int idx_off, int has_idx)
{
    extern __shared__ char sm[];
    float* Wc  = (float*)sm;                    // 32768 B  W chunk [128 d][64 v]
    float* buf = (float*)(sm + 32768);          // 33280 B  8 reduction tiles
    float* gts = (float*)(sm + 66048);          // 4096 B
    float* sgs = (float*)(sm + 70144);          // 4096 B
    float* x1s = (float*)(sm + 74240);          // 131200 B [32][1025]

    const int tid  = threadIdx.x;
    const int lane = tid & 31;
    const int wid  = tid >> 5;                  // 0..15
    const int t0   = blockIdx.x * TM;

    for (int i = tid; i < Dn; i += NT) { gts[i] = gate[i]; sgs[i] = sgate[i]; }
    // idx dtype detect: int64 -> all high words zero; int32 -> values 0..63 everywhere.
    int is32 = __syncthreads_or(iw[2 * tid + 1] != 0);

    // ---------------- Phase A: gated blend; x1 -> smem; soft-gate means ----------------
    float sgv[2];
    #pragma unroll
    for (int j = 0; j < 2; j++) {
        const int tl = 2 * wid + j;
        const int tg = t0 + tl;
        const float* xr = xg + (size_t)tg * Dn;
        float xv[32];
        #pragma unroll
        for (int k = 0; k < 32; k++) xv[k] = xr[lane + 32 * k];   // deep MLP batch
        float s = 0.f;
        #pragma unroll
        for (int k = 0; k < 32; k++) s += sigmoid_f(xv[k] * gts[lane + 32 * k]);
        #pragma unroll
        for (int o = 16; o; o >>= 1) s += __shfl_xor_sync(0xffffffffu, s, o);
        float g = s * (1.0f / 1024.0f);

        int it = is32 ? iw[tg] : iw[2 * tg];
        it = min(max(it, 0), Vn - 1);
        const float* er = emb + (size_t)it * Dn;

        float ss = 0.f;
        float* xs = x1s + tl * XP;
        #pragma unroll
        for (int k = 0; k < 32; k++) {
            int d = lane + 32 * k;
            float x1 = fmaf(er[d] - xv[k], g, xv[k]);
            xs[d] = x1;
            ss += sigmoid_f(x1 * sgs[d]);
        }
        #pragma unroll
        for (int o = 16; o; o >>= 1) ss += __shfl_xor_sync(0xffffffffu, ss, o);
        sgv[j] = ss * (1.0f / 1024.0f);
    }
    __syncthreads();

    // ---------------- Phase B: logits GEMM (outer-product, d-split) ----------------
    const int a    = lane >> 3;      // token sub-group
    const int b    = lane & 7;       // vocab group (8 v)
    const int half = wid >> 3;       // token half
    const int wd   = wid & 7;        // 16-d slice within chunk

    unsigned long long acc[4][4];
    #pragma unroll
    for (int t = 0; t < 4; t++)
        #pragma unroll
        for (int gg = 0; gg < 4; gg++) acc[t][gg] = 0ull;

    const float* xb = x1s + (half * 16 + 4 * a) * XP;

    for (int c = 0; c < NCH; c++) {
        const float4* src = (const float4*)(g_wt + c * CD * Vn);
        float4* dst = (float4*)Wc;
        #pragma unroll
        for (int i = 0; i < 4; i++) dst[tid + i * NT] = src[tid + i * NT];
        __syncthreads();

        const float* xp = xb + c * CD + wd * 16;
        const char*  wp = (const char*)(Wc + (wd * 16) * Vn + 8 * b);
        #pragma unroll
        for (int i = 0; i < 16; i++) {
            unsigned long long xd0 = packdup(xp[i]);
            unsigned long long xd1 = packdup(xp[XP + i]);
            unsigned long long xd2 = packdup(xp[2 * XP + i]);
            unsigned long long xd3 = packdup(xp[3 * XP + i]);
            const ulonglong2* wr = (const ulonglong2*)(wp + i * (Vn * 4));
            ulonglong2 wA = wr[0];
            ulonglong2 wB = wr[1];
            acc[0][0] = ffma2(xd0, wA.x, acc[0][0]);
            acc[1][0] = ffma2(xd1, wA.x, acc[1][0]);
            acc[2][0] = ffma2(xd2, wA.x, acc[2][0]);
            acc[3][0] = ffma2(xd3, wA.x, acc[3][0]);
            acc[0][1] = ffma2(xd0, wA.y, acc[0][1]);
            acc[1][1] = ffma2(xd1, wA.y, acc[1][1]);
            acc[2][1] = ffma2(xd2, wA.y, acc[2][1]);
            acc[3][1] = ffma2(xd3, wA.y, acc[3][1]);
            acc[0][2] = ffma2(xd0, wB.x, acc[0][2]);
            acc[1][2] = ffma2(xd1, wB.x, acc[1][2]);
            acc[2][2] = ffma2(xd2, wB.x, acc[2][2]);
            acc[3][2] = ffma2(xd3, wB.x, acc[3][2]);
            acc[0][3] = ffma2(xd0, wB.y, acc[0][3]);
            acc[1][3] = ffma2(xd1, wB.y, acc[1][3]);
            acc[2][3] = ffma2(xd2, wB.y, acc[2][3]);
            acc[3][3] = ffma2(xd3, wB.y, acc[3][3]);
        }
        __syncthreads();
    }

    float la[4][8];
    #pragma unroll
    for (int t = 0; t < 4; t++)
        #pragma unroll
        for (int gg = 0; gg < 4; gg++) {
            la[t][2 * gg]     = f2lo(acc[t][gg]);
            la[t][2 * gg + 1] = f2hi(acc[t][gg]);
        }

    // ---------------- cross-warp reduction: per half, 8 partials -> slots 0,1 ----------
    const int sb = half * 4;
    #define TSTORE(SLOT)                                                          \
        { float* bp = buf + (SLOT) * TILE_F + (4 * a) * TPAD + 8 * b;             \
          _Pragma("unroll") for (int t = 0; t < 4; t++)                           \
          _Pragma("unroll") for (int vv = 0; vv < 8; vv++)                        \
              bp[t * TPAD + vv] = la[t][vv]; }
    #define TADD(SLOT)                                                            \
        { const float* bp = buf + (SLOT) * TILE_F + (4 * a) * TPAD + 8 * b;       \
          _Pragma("unroll") for (int t = 0; t < 4; t++)                           \
          _Pragma("unroll") for (int vv = 0; vv < 8; vv++)                        \
              la[t][vv] += bp[t * TPAD + vv]; }

    if (wd >= 4) TSTORE(sb + wd - 4);
    __syncthreads();
    if (wd < 4) { TADD(sb + wd); }
    __syncthreads();
    if (wd == 2 || wd == 3) TSTORE(sb + wd - 2);
    __syncthreads();
    if (wd < 2) { TADD(sb + wd); TSTORE(sb + wd); }
    __syncthreads();

    // ---------------- Phase C: argmax + peaked softmax ----------------
    float p0a[2], p1a[2];
    unsigned m0a[2], m1a[2];
    #pragma unroll
    for (int j = 0; j < 2; j++) {
        const int tl   = 2 * wid + j;
        const int hh   = tl >> 4;
        const int tloc = tl & 15;
        const float* b0 = buf + (hh * 4 + 0) * TILE_F + tloc * TPAD;
        const float* b1 = buf + (hh * 4 + 1) * TILE_F + tloc * TPAD;
        float l0 = b0[2 * lane] + b1[2 * lane];
        float l1 = b0[2 * lane + 1] + b1[2 * lane + 1];

        float m = l0; int mi = 2 * lane;
        if (l1 > m) { m = l1; mi = 2 * lane + 1; }
        #pragma unroll
        for (int o = 16; o; o >>= 1) {
            float om = __shfl_xor_sync(0xffffffffu, m, o);
            int  omi = __shfl_xor_sync(0xffffffffu, mi, o);
            if (om > m || (om == m && omi < mi)) { m = om; mi = omi; }
        }
        float e0 = __expf(l0 - m), e1 = __expf(l1 - m);
        float den = e0 + e1;
        #pragma unroll
        for (int o = 16; o; o >>= 1) den += __shfl_xor_sync(0xffffffffu, den, o);
        float rd = 1.0f / den;
        float p0 = e0 * rd, p1 = e1 * rd;
        p0a[j] = p0; p1a[j] = p1;
        m0a[j] = __ballot_sync(0xffffffffu, p0 > PTHRESH);
        m1a[j] = __ballot_sync(0xffffffffu, p1 > PTHRESH);
        if (has_idx && lane == 0) out[(size_t)idx_off + (t0 + tl)] = (float)mi;
    }

    // ---------------- Phase D: sparse soft_emb gather + final blend + store ------------
    #pragma unroll
    for (int j = 0; j < 2; j++) {
        const int tl = 2 * wid + j;
        const int tg = t0 + tl;
        const float sgj = sgv[j];
        const float* xs = x1s + tl * XP;
        float* orow = out + (size_t)tg * Dn;
        for (int c = 0; c < 4; c++) {
            float av[8];
            #pragma unroll
            for (int i = 0; i < 8; i++) av[i] = 0.f;
            unsigned mm = m0a[j];
            while (mm) {                         // uniform trip count (from ballot)
                int bb = __ffs(mm) - 1; mm &= mm - 1;
                float p = __shfl_sync(0xffffffffu, p0a[j], bb);
                const float* er = emb + (size_t)(2 * bb) * Dn + c * 256 + lane;
                #pragma unroll
                for (int i = 0; i < 8; i++) av[i] = fmaf(p, __ldg(er + 32 * i), av[i]);
            }
            mm = m1a[j];
            while (mm) {
                int bb = __ffs(mm) - 1; mm &= mm - 1;
                float p = __shfl_sync(0xffffffffu, p1a[j], bb);
                const float* er = emb + (size_t)(2 * bb + 1) * Dn + c * 256 + lane;
                #pragma unroll
                for (int i = 0; i < 8; i++) av[i] = fmaf(p, __ldg(er + 32 * i), av[i]);
            }
            #pragma unroll
            for (int i = 0; i < 8; i++) {
                int d = c * 256 + lane + 32 * i;
                float xv = xs[d];
                orow[d] = fmaf(sgj, av[i] - xv, xv);
            }
        }
    }
}

extern "C" void kernel_launch(void* const* d_in, const int* in_sizes, int n_in,
                              void* d_out, int out_size) {
    (void)n_in;
    const float* x     = (const float*)d_in[0];
    const int*   idx   = (const int*)d_in[1];
    const float* emb   = (const float*)d_in[2];
    const float* hw    = (const float*)d_in[3];
    const float* gate  = (const float*)d_in[4];
    const float* sgate = (const float*)d_in[5];
    float* out = (float*)d_out;

    const int n_tok   = in_sizes[0] / Dn;
    const int idx_off = in_sizes[0];
    const int has_idx = (out_size >= idx_off + n_tok) ? 1 : 0;

    const int smem_bytes = 74240 + TM * XP * 4;   // 205440
    cudaFuncSetAttribute(k_fused, cudaFuncAttributeMaxDynamicSharedMemorySize, smem_bytes);

    k_tr<<<Dn / 64, 256>>>(hw);
    k_fused<<<n_tok / TM, NT, smem_bytes>>>(x, idx, emb, gate, sgate, out,
                                            idx_off, has_idx);
}

// round 4
// speedup vs baseline: 3.2972x; 1.4101x over previous
#include <cuda_runtime.h>
#include <cstdint>

#define Dn 1024
#define Vn 64
#define TM 16
#define NT 512
#define XP 1026              // x1 row stride (floats), even for LDS.64
#define TP 36                // reduction tile row pad (floats), 16B-multiple rows
#define SLOT_F (16 * TP)     // 576 floats per partial tile (16 tok x 32 v + pad)
#define PTHRESH 1e-8f

// head_weight transposed: g_wt[d*64 + v] = hw[v*1024 + d]
__device__ __align__(16) float g_wt[Dn * Vn];

__global__ void k_tr(const float* __restrict__ hw) {
    __shared__ float t[64][65];
    const int d0 = blockIdx.x * 64;
    const int c  = threadIdx.x & 63;
    const int r4 = threadIdx.x >> 6;
    #pragma unroll
    for (int i = 0; i < 16; i++) {
        int v = r4 * 16 + i;
        t[c][v] = hw[v * Dn + d0 + c];
    }
    __syncthreads();
    #pragma unroll
    for (int i = 0; i < 16; i++) {
        int dd = r4 * 16 + i;
        g_wt[(d0 + dd) * Vn + c] = t[dd][c];
    }
}

__device__ __forceinline__ unsigned long long ffma2(unsigned long long a,
                                                    unsigned long long b,
                                                    unsigned long long c) {
    unsigned long long d;
    asm("fma.rn.f32x2 %0, %1, %2, %3;" : "=l"(d) : "l"(a), "l"(b), "l"(c));
    return d;
}
__device__ __forceinline__ unsigned long long packdup(float x) {
    unsigned long long d;
    unsigned u = __float_as_uint(x);
    asm("mov.b64 %0, {%1, %1};" : "=l"(d) : "r"(u));
    return d;
}
__device__ __forceinline__ float f2lo(unsigned long long a) { return __uint_as_float((unsigned)a); }
__device__ __forceinline__ float f2hi(unsigned long long a) { return __uint_as_float((unsigned)(a >> 32)); }

__device__ __forceinline__ float sigmoid_f(float z) {
    float z2 = z * z;
    float p = fmaf(z, fmaf(z2, fmaf(z2, 0.00208333333f, -0.0208333333f), 0.25f), 0.5f);
    if (fabsf(z) > 0.35f) p = 1.0f / (1.0f + __expf(-z));
    return p;
}

__global__ void __launch_bounds__(NT, 2)
k_fused(const float* __restrict__ xg, const int* __restrict__ iw,
        const float* __restrict__ emb, const float* __restrict__ gate,
        const float* __restrict__ sgate, float* __restrict__ out,
        int idx_off, int has_idx)
{
    extern __shared__ char sm[];
    float* x1s = (float*)sm;                        // 65664 B  [16][1026]
    float* buf = (float*)(sm + 65664);              // 18432 B  8 tiles [16][36]
    float* gts = (float*)(sm + 65664 + 18432);      // 4096 B
    float* sgs = gts + Dn;                          // 4096 B

    const int tid  = threadIdx.x;
    const int lane = tid & 31;
    const int wid  = tid >> 5;                      // 0..15
    const int t0   = blockIdx.x * TM;

    for (int i = tid; i < Dn; i += NT) { gts[i] = gate[i]; sgs[i] = sgate[i]; }
    // idx dtype: int64 -> high words all zero; int32 -> values 0..63 everywhere.
    int is32 = __syncthreads_or(iw[2 * tid + 1] != 0);

    // ---------------- Phase A: warp = one token; gated blend; x1 -> smem ----------------
    float sgv;
    {
        const int tg = t0 + wid;
        const float* xr = xg + (size_t)tg * Dn;
        float xv[32];
        #pragma unroll
        for (int k = 0; k < 32; k++) xv[k] = xr[lane + 32 * k];   // deep MLP batch
        float s = 0.f;
        #pragma unroll
        for (int k = 0; k < 32; k++) s += sigmoid_f(xv[k] * gts[lane + 32 * k]);
        #pragma unroll
        for (int o = 16; o; o >>= 1) s += __shfl_xor_sync(0xffffffffu, s, o);
        float g = s * (1.0f / 1024.0f);

        int it = is32 ? iw[tg] : iw[2 * tg];
        it = min(max(it, 0), Vn - 1);
        const float* er = emb + (size_t)it * Dn;

        float ss = 0.f;
        float* xs = x1s + wid * XP;
        #pragma unroll
        for (int k = 0; k < 32; k++) {
            int d = lane + 32 * k;
            float x1 = fmaf(er[d] - xv[k], g, xv[k]);
            xs[d] = x1;
            ss += sigmoid_f(x1 * sgs[d]);
        }
        #pragma unroll
        for (int o = 16; o; o >>= 1) ss += __shfl_xor_sync(0xffffffffu, ss, o);
        sgv = ss * (1.0f / 1024.0f);
    }
    __syncthreads();

    // ---------------- Phase B: logits GEMM ----------------
    // warp: vhalf = wid>>3 (32 v), dslice = wid&7 (128 d).  W straight from L2 (LDG.128).
    // lane: tg = lane>>2 -> tokens {2tg, 2tg+1}; vg = lane&3 -> 8 v.
    const int tg2   = (lane >> 2) * 2;
    const int vg    = lane & 3;
    const int vhalf = wid >> 3;
    const int dbase = (wid & 7) * 128;
    const int vbase = vhalf * 32 + 8 * vg;

    unsigned long long acc[2][4];
    #pragma unroll
    for (int t = 0; t < 2; t++)
        #pragma unroll
        for (int gq = 0; gq < 4; gq++) acc[t][gq] = 0ull;

    const float2* xq0 = (const float2*)(x1s + (tg2 + 0) * XP + dbase);
    const float2* xq1 = (const float2*)(x1s + (tg2 + 1) * XP + dbase);
    const ulonglong2* wq = (const ulonglong2*)(g_wt + dbase * Vn + vbase);

    #pragma unroll 4
    for (int ss = 0; ss < 64; ss++) {             // 2 d per step, 128 d total
        float2 xa = xq0[ss];
        float2 xb = xq1[ss];
        ulonglong2 w0a = wq[32 * ss];             // d = dbase+2ss,   v = vbase..+3
        ulonglong2 w0b = wq[32 * ss + 1];         //                  v = vbase+4..+7
        ulonglong2 w1a = wq[32 * ss + 16];        // d = dbase+2ss+1
        ulonglong2 w1b = wq[32 * ss + 17];
        unsigned long long xl0 = packdup(xa.x), xh0 = packdup(xa.y);
        unsigned long long xl1 = packdup(xb.x), xh1 = packdup(xb.y);
        acc[0][0] = ffma2(xl0, w0a.x, acc[0][0]);
        acc[0][1] = ffma2(xl0, w0a.y, acc[0][1]);
        acc[0][2] = ffma2(xl0, w0b.x, acc[0][2]);
        acc[0][3] = ffma2(xl0, w0b.y, acc[0][3]);
        acc[1][0] = ffma2(xl1, w0a.x, acc[1][0]);
        acc[1][1] = ffma2(xl1, w0a.y, acc[1][1]);
        acc[1][2] = ffma2(xl1, w0b.x, acc[1][2]);
        acc[1][3] = ffma2(xl1, w0b.y, acc[1][3]);
        acc[0][0] = ffma2(xh0, w1a.x, acc[0][0]);
        acc[0][1] = ffma2(xh0, w1a.y, acc[0][1]);
        acc[0][2] = ffma2(xh0, w1b.x, acc[0][2]);
        acc[0][3] = ffma2(xh0, w1b.y, acc[0][3]);
        acc[1][0] = ffma2(xh1, w1a.x, acc[1][0]);
        acc[1][1] = ffma2(xh1, w1a.y, acc[1][1]);
        acc[1][2] = ffma2(xh1, w1b.x, acc[1][2]);
        acc[1][3] = ffma2(xh1, w1b.y, acc[1][3]);
    }

    float la[2][8];
    #pragma unroll
    for (int t = 0; t < 2; t++)
        #pragma unroll
        for (int gq = 0; gq < 4; gq++) {
            la[t][2 * gq]     = f2lo(acc[t][gq]);
            la[t][2 * gq + 1] = f2hi(acc[t][gq]);
        }

    // ---------------- cross-warp reduction: per v-half, 8 d-partials -> slots 0,1 -------
    const int wd = wid & 7;
    const int sb = vhalf * 4;
    #define TSTORE(SLOT)                                                          \
        { float* bp = buf + (SLOT) * SLOT_F + tg2 * TP + 8 * vg;                  \
          _Pragma("unroll") for (int t = 0; t < 2; t++)                           \
          _Pragma("unroll") for (int vv = 0; vv < 8; vv++)                        \
              bp[t * TP + vv] = la[t][vv]; }
    #define TADD(SLOT)                                                            \
        { const float* bp = buf + (SLOT) * SLOT_F + tg2 * TP + 8 * vg;            \
          _Pragma("unroll") for (int t = 0; t < 2; t++)                           \
          _Pragma("unroll") for (int vv = 0; vv < 8; vv++)                        \
              la[t][vv] += bp[t * TP + vv]; }

    if (wd >= 4) TSTORE(sb + wd - 4);
    __syncthreads();
    if (wd < 4) { TADD(sb + wd); }
    __syncthreads();
    if (wd == 2 || wd == 3) TSTORE(sb + wd - 2);
    __syncthreads();
    if (wd < 2) { TADD(sb + wd); TSTORE(sb + wd); }
    __syncthreads();

    // ---------------- Phase C: warp = one token; argmax + peaked softmax ----------------
    float p0, p1;
    unsigned m0, m1;
    {
        const int vh = lane >> 4;                 // which v-half this lane's 2 v live in
        const float* bp = buf + (vh * 4) * SLOT_F + wid * TP + ((2 * lane) & 31);
        float l0 = bp[0] + bp[SLOT_F];
        float l1 = bp[1] + bp[SLOT_F + 1];

        float m = l0; int mi = 2 * lane;
        if (l1 > m) { m = l1; mi = 2 * lane + 1; }
        #pragma unroll
        for (int o = 16; o; o >>= 1) {
            float om = __shfl_xor_sync(0xffffffffu, m, o);
            int  omi = __shfl_xor_sync(0xffffffffu, mi, o);
            if (om > m || (om == m && omi < mi)) { m = om; mi = omi; }
        }
        float e0 = __expf(l0 - m), e1 = __expf(l1 - m);
        float den = e0 + e1;
        #pragma unroll
        for (int o = 16; o; o >>= 1) den += __shfl_xor_sync(0xffffffffu, den, o);
        float rd = 1.0f / den;
        p0 = e0 * rd; p1 = e1 * rd;
        m0 = __ballot_sync(0xffffffffu, p0 > PTHRESH);
        m1 = __ballot_sync(0xffffffffu, p1 > PTHRESH);
        if (has_idx && lane == 0) out[(size_t)idx_off + (t0 + wid)] = (float)mi;
    }

    // ---------------- Phase D: sparse soft_emb gather + final blend + store -------------
    {
        const int tg = t0 + wid;
        const float* xs = x1s + wid * XP;
        float* orow = out + (size_t)tg * Dn;
        for (int c = 0; c < 4; c++) {
            float av[8];
            #pragma unroll
            for (int i = 0; i < 8; i++) av[i] = 0.f;
            unsigned mm = m0;
            while (mm) {                          // uniform trip count (ballot-derived)
                int bb = __ffs(mm) - 1; mm &= mm - 1;
                float p = __shfl_sync(0xffffffffu, p0, bb);
                const float* er = emb + (size_t)(2 * bb) * Dn + c * 256 + lane;
                #pragma unroll
                for (int i = 0; i < 8; i++) av[i] = fmaf(p, __ldg(er + 32 * i), av[i]);
            }
            mm = m1;
            while (mm) {
                int bb = __ffs(mm) - 1; mm &= mm - 1;
                float p = __shfl_sync(0xffffffffu, p1, bb);
                const float* er = emb + (size_t)(2 * bb + 1) * Dn + c * 256 + lane;
                #pragma unroll
                for (int i = 0; i < 8; i++) av[i] = fmaf(p, __ldg(er + 32 * i), av[i]);
            }
            #pragma unroll
            for (int i = 0; i < 8; i++) {
                int d = c * 256 + lane + 32 * i;
                float xv = xs[d];
                orow[d] = fmaf(sgv, av[i] - xv, xv);
            }
        }
    }
}

extern "C" void kernel_launch(void* const* d_in, const int* in_sizes, int n_in,
                              void* d_out, int out_size) {
    (void)n_in;
    const float* x     = (const float*)d_in[0];
    const int*   idx   = (const int*)d_in[1];
    const float* emb   = (const float*)d_in[2];
    const float* hw    = (const float*)d_in[3];
    const float* gate  = (const float*)d_in[4];
    const float* sgate = (const float*)d_in[5];
    float* out = (float*)d_out;

    const int n_tok   = in_sizes[0] / Dn;
    const int idx_off = in_sizes[0];
    const int has_idx = (out_size >= idx_off + n_tok) ? 1 : 0;

    const int smem_bytes = 65664 + 18432 + 8192;   // 92288
    cudaFuncSetAttribute(k_fused, cudaFuncAttributeMaxDynamicSharedMemorySize, smem_bytes);

    k_tr<<<Dn / 64, 256>>>(hw);
    k_fused<<<n_tok / TM, NT, smem_bytes>>>(x, idx, emb, gate, sgate, out,
                                            idx_off, has_idx);
}

// round 5
// speedup vs baseline: 3.3653x; 1.0206x over previous
#include <cuda_runtime.h>
#include <cstdint>

#define Dn 1024
#define Vn 64
#define TM 32
#define NT 512
#define XROW 33              // xT row stride in float2 (per d-pair)
#define TP 36                // reduction tile row pad (floats)
#define SLOT_F (32 * TP)     // 1152 floats per partial tile (32 tok x 32 v)
#define PTHRESH 1e-8f

// head_weight transposed: g_wt[d*64 + v] = hw[v*1024 + d]
__device__ __align__(16) float g_wt[Dn * Vn];

__global__ void k_tr(const float* __restrict__ hw) {
    __shared__ float t[64][65];
    const int d0 = blockIdx.x * 64;
    const int c  = threadIdx.x & 63;
    const int r4 = threadIdx.x >> 6;
    #pragma unroll
    for (int i = 0; i < 16; i++) {
        int v = r4 * 16 + i;
        t[c][v] = hw[v * Dn + d0 + c];
    }
    __syncthreads();
    #pragma unroll
    for (int i = 0; i < 16; i++) {
        int dd = r4 * 16 + i;
        g_wt[(d0 + dd) * Vn + c] = t[dd][c];
    }
}

__device__ __forceinline__ unsigned long long ffma2(unsigned long long a,
                                                    unsigned long long b,
                                                    unsigned long long c) {
    unsigned long long d;
    asm("fma.rn.f32x2 %0, %1, %2, %3;" : "=l"(d) : "l"(a), "l"(b), "l"(c));
    return d;
}
__device__ __forceinline__ unsigned long long packdup(float x) {
    unsigned long long d;
    unsigned u = __float_as_uint(x);
    asm("mov.b64 %0, {%1, %1};" : "=l"(d) : "r"(u));
    return d;
}
__device__ __forceinline__ float f2lo(unsigned long long a) { return __uint_as_float((unsigned)a); }
__device__ __forceinline__ float f2hi(unsigned long long a) { return __uint_as_float((unsigned)(a >> 32)); }

__device__ __forceinline__ float sigmoid_f(float z) {
    float z2 = z * z;
    float p = fmaf(z, fmaf(z2, fmaf(z2, 0.00208333333f, -0.0208333333f), 0.25f), 0.5f);
    if (fabsf(z) > 0.35f) p = 1.0f / (1.0f + __expf(-z));
    return p;
}

__global__ void __launch_bounds__(NT, 1)
k_fused(const float* __restrict__ xg, const int* __restrict__ iw,
        const float* __restrict__ emb, const float* __restrict__ gate,
        const float* __restrict__ sgate, float* __restrict__ out,
        int idx_off, int has_idx)
{
    extern __shared__ char sm[];
    float2* xT  = (float2*)sm;                      // 135168 B [512 dp][33 f2]
    float*  buf = (float*)(sm + 135168);            // 36864 B  8 tiles [32][36]
    float2* g2  = (float2*)(sm + 135168 + 36864);   // 4096 B
    float2* sg2 = (float2*)(sm + 135168 + 36864 + 4096);  // 4096 B

    const int tid  = threadIdx.x;
    const int lane = tid & 31;
    const int wid  = tid >> 5;                      // 0..15
    const int t0   = blockIdx.x * TM;

    for (int i = tid; i < Dn / 2; i += NT) {
        g2[i]  = ((const float2*)gate)[i];
        sg2[i] = ((const float2*)sgate)[i];
    }
    // idx dtype: int64 -> high words all zero; int32 -> values 0..63 everywhere.
    int is32 = __syncthreads_or(iw[2 * tid + 1] != 0);

    // ---------------- Phase A: warp = 2 tokens; gated blend; x1 -> xT (d-pair major) ----
    float sgv[2];
    #pragma unroll
    for (int j = 0; j < 2; j++) {
        const int tl = 2 * wid + j;
        const int tg = t0 + tl;
        const int poff = (tl & 3) * 8 + (tl >> 2);          // permuted token slot
        const float2* xr2 = (const float2*)(xg + (size_t)tg * Dn);

        float2 xv[16];
        #pragma unroll
        for (int k = 0; k < 16; k++) xv[k] = xr2[lane + 32 * k];   // deep MLP batch
        float s = 0.f;
        #pragma unroll
        for (int k = 0; k < 16; k++) {
            float2 gg = g2[lane + 32 * k];
            s += sigmoid_f(xv[k].x * gg.x) + sigmoid_f(xv[k].y * gg.y);
        }
        #pragma unroll
        for (int o = 16; o; o >>= 1) s += __shfl_xor_sync(0xffffffffu, s, o);
        float g = s * (1.0f / 1024.0f);

        int it = is32 ? iw[tg] : iw[2 * tg];
        it = min(max(it, 0), Vn - 1);
        const float2* er2 = (const float2*)(emb + (size_t)it * Dn);

        float ss = 0.f;
        #pragma unroll
        for (int k = 0; k < 16; k++) {
            int dp = lane + 32 * k;
            float2 e2 = __ldg(er2 + dp);
            float2 x1;
            x1.x = fmaf(e2.x - xv[k].x, g, xv[k].x);
            x1.y = fmaf(e2.y - xv[k].y, g, xv[k].y);
            xT[dp * XROW + poff] = x1;
            float2 sgc = sg2[dp];
            ss += sigmoid_f(x1.x * sgc.x) + sigmoid_f(x1.y * sgc.y);
        }
        #pragma unroll
        for (int o = 16; o; o >>= 1) ss += __shfl_xor_sync(0xffffffffu, ss, o);
        sgv[j] = ss * (1.0f / 1024.0f);
    }
    __syncthreads();

    // ---------------- Phase B: logits GEMM (32 tok x 32 v x 128 d per warp) -------------
    const int tg    = lane >> 2;     // 8 token-groups (4 consecutive tokens each)
    const int vg    = lane & 3;      // 4 v-groups (8 v each)
    const int vhalf = wid >> 3;
    const int wd    = wid & 7;       // 128-d slice

    unsigned long long acc[4][4];
    #pragma unroll
    for (int t = 0; t < 4; t++)
        #pragma unroll
        for (int q = 0; q < 4; q++) acc[t][q] = 0ull;

    const float2* xTb = xT + (wd * 64) * XROW;
    const ulonglong2* wq =
        (const ulonglong2*)(g_wt + (wd * 128) * Vn + vhalf * 32 + vg * 8);

    #pragma unroll 4
    for (int ss = 0; ss < 64; ss++) {              // dp = wd*64 + ss; d = 2dp, 2dp+1
        const float2* row = xTb + ss * XROW;
        float2 xa0 = row[0 * 8 + tg];
        float2 xa1 = row[1 * 8 + tg];
        float2 xa2 = row[2 * 8 + tg];
        float2 xa3 = row[3 * 8 + tg];
        ulonglong2 w0  = wq[(2 * ss) * 16];        // d even, v +0..+3
        ulonglong2 w0b = wq[(2 * ss) * 16 + 1];    // d even, v +4..+7
        ulonglong2 w1  = wq[(2 * ss + 1) * 16];    // d odd
        ulonglong2 w1b = wq[(2 * ss + 1) * 16 + 1];

        unsigned long long xl, xh;
        xl = packdup(xa0.x); xh = packdup(xa0.y);
        acc[0][0] = ffma2(xl, w0.x,  acc[0][0]);
        acc[0][1] = ffma2(xl, w0.y,  acc[0][1]);
        acc[0][2] = ffma2(xl, w0b.x, acc[0][2]);
        acc[0][3] = ffma2(xl, w0b.y, acc[0][3]);
        acc[0][0] = ffma2(xh, w1.x,  acc[0][0]);
        acc[0][1] = ffma2(xh, w1.y,  acc[0][1]);
        acc[0][2] = ffma2(xh, w1b.x, acc[0][2]);
        acc[0][3] = ffma2(xh, w1b.y, acc[0][3]);
        xl = packdup(xa1.x); xh = packdup(xa1.y);
        acc[1][0] = ffma2(xl, w0.x,  acc[1][0]);
        acc[1][1] = ffma2(xl, w0.y,  acc[1][1]);
        acc[1][2] = ffma2(xl, w0b.x, acc[1][2]);
        acc[1][3] = ffma2(xl, w0b.y, acc[1][3]);
        acc[1][0] = ffma2(xh, w1.x,  acc[1][0]);
        acc[1][1] = ffma2(xh, w1.y,  acc[1][1]);
        acc[1][2] = ffma2(xh, w1b.x, acc[1][2]);
        acc[1][3] = ffma2(xh, w1b.y, acc[1][3]);
        xl = packdup(xa2.x); xh = packdup(xa2.y);
        acc[2][0] = ffma2(xl, w0.x,  acc[2][0]);
        acc[2][1] = ffma2(xl, w0.y,  acc[2][1]);
        acc[2][2] = ffma2(xl, w0b.x, acc[2][2]);
        acc[2][3] = ffma2(xl, w0b.y, acc[2][3]);
        acc[2][0] = ffma2(xh, w1.x,  acc[2][0]);
        acc[2][1] = ffma2(xh, w1.y,  acc[2][1]);
        acc[2][2] = ffma2(xh, w1b.x, acc[2][2]);
        acc[2][3] = ffma2(xh, w1b.y, acc[2][3]);
        xl = packdup(xa3.x); xh = packdup(xa3.y);
        acc[3][0] = ffma2(xl, w0.x,  acc[3][0]);
        acc[3][1] = ffma2(xl, w0.y,  acc[3][1]);
        acc[3][2] = ffma2(xl, w0b.x, acc[3][2]);
        acc[3][3] = ffma2(xl, w0b.y, acc[3][3]);
        acc[3][0] = ffma2(xh, w1.x,  acc[3][0]);
        acc[3][1] = ffma2(xh, w1.y,  acc[3][1]);
        acc[3][2] = ffma2(xh, w1b.x, acc[3][2]);
        acc[3][3] = ffma2(xh, w1b.y, acc[3][3]);
    }

    float la[4][8];
    #pragma unroll
    for (int t = 0; t < 4; t++)
        #pragma unroll
        for (int q = 0; q < 4; q++) {
            la[t][2 * q]     = f2lo(acc[t][q]);
            la[t][2 * q + 1] = f2hi(acc[t][q]);
        }

    // ---------------- cross-warp reduction: per v-half, 8 d-partials -> slots 0,1 -------
    const int sb = vhalf * 4;
    #define TSTORE(SLOT)                                                          \
        { float* bp = buf + (SLOT) * SLOT_F + (4 * tg) * TP + 8 * vg;             \
          _Pragma("unroll") for (int t = 0; t < 4; t++)                           \
          _Pragma("unroll") for (int vv = 0; vv < 8; vv++)                        \
              bp[t * TP + vv] = la[t][vv]; }
    #define TADD(SLOT)                                                            \
        { const float* bp = buf + (SLOT) * SLOT_F + (4 * tg) * TP + 8 * vg;       \
          _Pragma("unroll") for (int t = 0; t < 4; t++)                           \
          _Pragma("unroll") for (int vv = 0; vv < 8; vv++)                        \
              la[t][vv] += bp[t * TP + vv]; }

    if (wd >= 4) TSTORE(sb + wd - 4);
    __syncthreads();
    if (wd < 4) { TADD(sb + wd); }
    __syncthreads();
    if (wd == 2 || wd == 3) TSTORE(sb + wd - 2);
    __syncthreads();
    if (wd < 2) { TADD(sb + wd); TSTORE(sb + wd); }
    __syncthreads();

    // ---------------- Phase C: warp = 2 tokens; argmax + peaked softmax -----------------
    float p0a[2], p1a[2];
    unsigned m0a[2], m1a[2];
    #pragma unroll
    for (int j = 0; j < 2; j++) {
        const int tl = 2 * wid + j;
        const int vh = lane >> 4;
        const float* bp = buf + (vh * 4) * SLOT_F + tl * TP + ((2 * lane) & 31);
        float l0 = bp[0] + bp[SLOT_F];
        float l1 = bp[1] + bp[SLOT_F + 1];

        float m = l0; int mi = 2 * lane;
        if (l1 > m) { m = l1; mi = 2 * lane + 1; }
        #pragma unroll
        for (int o = 16; o; o >>= 1) {
            float om = __shfl_xor_sync(0xffffffffu, m, o);
            int  omi = __shfl_xor_sync(0xffffffffu, mi, o);
            if (om > m || (om == m && omi < mi)) { m = om; mi = omi; }
        }
        float e0 = __expf(l0 - m), e1 = __expf(l1 - m);
        float den = e0 + e1;
        #pragma unroll
        for (int o = 16; o; o >>= 1) den += __shfl_xor_sync(0xffffffffu, den, o);
        float rd = 1.0f / den;
        float p0 = e0 * rd, p1 = e1 * rd;
        p0a[j] = p0; p1a[j] = p1;
        m0a[j] = __ballot_sync(0xffffffffu, p0 > PTHRESH);
        m1a[j] = __ballot_sync(0xffffffffu, p1 > PTHRESH);
        if (has_idx && lane == 0) out[(size_t)idx_off + (t0 + tl)] = (float)mi;
    }

    // ---------------- Phase D: sparse soft_emb gather + final blend + store -------------
    #pragma unroll
    for (int j = 0; j < 2; j++) {
        const int tl = 2 * wid + j;
        const int tg2 = t0 + tl;
        const int poff = (tl & 3) * 8 + (tl >> 2);
        const float sgj = sgv[j];
        float2* orow = (float2*)(out + (size_t)tg2 * Dn);
        for (int c = 0; c < 4; c++) {
            float2 av[4];
            #pragma unroll
            for (int i = 0; i < 4; i++) { av[i].x = 0.f; av[i].y = 0.f; }
            unsigned mm = m0a[j];
            while (mm) {                          // uniform trip count (ballot-derived)
                int bb = __ffs(mm) - 1; mm &= mm - 1;
                float p = __shfl_sync(0xffffffffu, p0a[j], bb);
                const float2* er = (const float2*)(emb + (size_t)(2 * bb) * Dn)
                                   + c * 128 + lane;
                #pragma unroll
                for (int i = 0; i < 4; i++) {
                    float2 e = __ldg(er + 32 * i);
                    av[i].x = fmaf(p, e.x, av[i].x);
                    av[i].y = fmaf(p, e.y, av[i].y);
                }
            }
            mm = m1a[j];
            while (mm) {
                int bb = __ffs(mm) - 1; mm &= mm - 1;
                float p = __shfl_sync(0xffffffffu, p1a[j], bb);
                const float2* er = (const float2*)(emb + (size_t)(2 * bb + 1) * Dn)
                                   + c * 128 + lane;
                #pragma unroll
                for (int i = 0; i < 4; i++) {
                    float2 e = __ldg(er + 32 * i);
                    av[i].x = fmaf(p, e.x, av[i].x);
                    av[i].y = fmaf(p, e.y, av[i].y);
                }
            }
            #pragma unroll
            for (int i = 0; i < 4; i++) {
                int dp = c * 128 + lane + 32 * i;
                float2 xv = xT[dp * XROW + poff];
                float2 r;
                r.x = fmaf(sgj, av[i].x - xv.x, xv.x);
                r.y = fmaf(sgj, av[i].y - xv.y, xv.y);
                orow[dp] = r;
            }
        }
    }
}

extern "C" void kernel_launch(void* const* d_in, const int* in_sizes, int n_in,
                              void* d_out, int out_size) {
    (void)n_in;
    const float* x     = (const float*)d_in[0];
    const int*   idx   = (const int*)d_in[1];
    const float* emb   = (const float*)d_in[2];
    const float* hw    = (const float*)d_in[3];
    const float* gate  = (const float*)d_in[4];
    const float* sgate = (const float*)d_in[5];
    float* out = (float*)d_out;

    const int n_tok   = in_sizes[0] / Dn;
    const int idx_off = in_sizes[0];
    const int has_idx = (out_size >= idx_off + n_tok) ? 1 : 0;

    const int smem_bytes = 135168 + 36864 + 4096 + 4096;   // 180224
    cudaFuncSetAttribute(k_fused, cudaFuncAttributeMaxDynamicSharedMemorySize, smem_bytes);

    k_tr<<<Dn / 64, 256>>>(hw);
    k_fused<<<n_tok / TM, NT, smem_bytes>>>(x, idx, emb, gate, sgate, out,
                                            idx_off, has_idx);
}